// round 12
// baseline (speedup 1.0000x reference)
#include <cuda_runtime.h>
#include <cuda_fp16.h>
#include <stdint.h>

#define NR  65536
#define KC  8192
#define DIM 256
#define ND  (NR*DIM)
#define CAP 64
#define MARGIN 3e-4f

__device__ float  g_znorm[NR];
__device__ int    g_idx[NR];
__device__ double g_part[NR];
__device__ double g_part2[128];
__device__ int    g_cnt[NR];
__device__ int    g_cand[(size_t)NR*CAP];
__device__ float  g_candd[(size_t)NR*CAP];
__device__ __align__(128) int8_t g_zq[ND];
__device__ __align__(128) int8_t g_wq[KC*DIM];

// dist = znorm - 2*z.W ;  z ~ z_q*(6/127), W ~ W_q/(127*8192)
// => dist ~= znorm - dot_q * 12/(127*127*8192)
#define SCALE_NEG (-(12.0f/132128768.0f))

__device__ __forceinline__ uint32_t smem_u32(const void* p) {
    uint32_t a;
    asm("{ .reg .u64 t; cvta.to.shared.u64 t, %1; cvt.u32.u64 %0, t; }" : "=r"(a) : "l"(p));
    return a;
}
__device__ __forceinline__ void cp16(uint32_t dst, const void* src) {
    asm volatile("cp.async.cg.shared.global [%0], [%1], 16;" :: "r"(dst), "l"(src) : "memory");
}
#define CPC() asm volatile("cp.async.commit_group;" ::: "memory")
#define CPW() asm volatile("cp.async.wait_group 0;" ::: "memory")
#define LDSM4(r0,r1,r2,r3,a) \
    asm volatile("ldmatrix.sync.aligned.m8n8.x4.shared.b16 {%0,%1,%2,%3}, [%4];" \
        : "=r"(r0),"=r"(r1),"=r"(r2),"=r"(r3) : "r"(a))
// int8 IMMA: s32 accum (exact), K=32 per instruction
#define MMAI(d,a0,a1,a2,a3,b0,b1) \
    asm volatile("mma.sync.aligned.m16n8k32.row.col.s32.s8.s8.s32 " \
        "{%0,%1,%2,%3}, {%4,%5,%6,%7}, {%8,%9}, {%0,%1,%2,%3};" \
        : "+r"((d)[0]),"+r"((d)[1]),"+r"((d)[2]),"+r"((d)[3]) \
        : "r"(a0),"r"(a1),"r"(a2),"r"(a3),"r"(b0),"r"(b1))

// ---- per-row ||z||^2 (validated order) + z->int8 + zero capture counters ----
__global__ void znorm_kernel(const float* __restrict__ z) {
    int warp = threadIdx.x >> 5, lane = threadIdx.x & 31;
    int row  = blockIdx.x * 8 + warp;
    const float* zr = z + (size_t)row * DIM;
    float s = 0.0f;
    #pragma unroll
    for (int t = 0; t < 8; t++) {
        float v = zr[t * 32 + lane];
        int q = __float2int_rn(v * 21.166666667f);   // 127/6
        q = max(-127, min(127, q));
        g_zq[(size_t)row * DIM + t * 32 + lane] = (int8_t)q;
        s = __fadd_rn(s, __fmul_rn(v, v));
    }
    #pragma unroll
    for (int off = 16; off > 0; off >>= 1)
        s = __fadd_rn(s, __shfl_xor_sync(0xffffffffu, s, off));
    if (lane == 0) { g_znorm[row] = s; g_cnt[row] = 0; }
}
// ---- W -> int8: rint(W * 8192 * 127) ----
__global__ void wconv_kernel(const float* __restrict__ W) {
    int i = blockIdx.x * 256 + threadIdx.x;
    int q = __float2int_rn(W[i] * 1040384.0f);
    q = max(-127, min(127, q));
    g_wq[i] = (int8_t)q;
}
// ---- dummy: keeps phase1 in ncu's capture slot ----
__global__ void dummy_kernel() { if (threadIdx.x > 9999) g_part2[0] = 0.0; }

// ---- Phase 1: int8 IMMA + candidate capture ----
// CTA = 64 rows x all codes, chunks of 64 codes. 8 warps: 4(m) x 2(n).
// smem: A 16KB @0, B 2x16KB @16384 (48KB -> 3 CTA/SM).
// int8 rows = 256B = 16 chunks of 16B; swizzle off(r,c16)=r*256+((c16^(r&7))<<4)
// s8 m16n8k32 fragments == b16 m16n8k16 fragments byte-for-byte (k doubled),
// so the validated f16 ldmatrix addressing carries over unchanged.
__global__ __launch_bounds__(256) void phase1_kernel() {
    extern __shared__ __align__(128) char sm[];
    const int tid = threadIdx.x, lane = tid & 31, wid = tid >> 5;
    const int wm = (wid & 3) * 16, wn = (wid >> 2) * 32;
    const int rowbase = blockIdx.x * 64;
    const uint32_t sb = smem_u32(sm);

    for (int i = tid; i < 1024; i += 256) {          // stage A (z rows, 16KB)
        int r = i >> 4, c = i & 15;
        cp16(sb + r*256 + ((c ^ (r&7)) << 4), g_zq + (size_t)(rowbase+r)*DIM + c*16);
    }
    for (int i = tid; i < 1024; i += 256) {          // stage B chunk 0
        int r = i >> 4, c = i & 15;
        cp16(sb + 16384 + r*256 + ((c ^ (r&7)) << 4), g_wq + (size_t)r*DIM + c*16);
    }
    CPC();

    const float zn_lo = g_znorm[rowbase + wm + (lane >> 2)];
    const float zn_hi = g_znorm[rowbase + wm + 8 + (lane >> 2)];
    float rm_lo = 3.4e38f, rm_hi = 3.4e38f;

    const int ar  = wm + (lane & 15);
    const int ac1 = lane >> 4;
    const uint32_t aBase = sb + ar * 256;
    const int arq = ar & 7;
    const int brl = (lane & 7) + ((lane & 16) >> 1);
    const int bc1 = (lane >> 3) & 1;

    for (int ch = 0; ch < 128; ch++) {
        const uint32_t bB = sb + 16384 + (ch & 1) * 16384;
        CPW(); __syncthreads();
        if (ch + 1 < 128) {
            const uint32_t nb = sb + 16384 + ((ch & 1) ^ 1) * 16384;
            const int8_t* src = g_wq + (size_t)(ch + 1) * 64 * DIM;
            for (int i = tid; i < 1024; i += 256) {
                int r = i >> 4, c = i & 15;
                cp16(nb + r*256 + ((c ^ (r&7)) << 4), src + r*DIM + c*16);
            }
            CPC();
        }
        int acc[4][4];
        #pragma unroll
        for (int j = 0; j < 4; j++)
            #pragma unroll
            for (int p = 0; p < 4; p++) acc[j][p] = 0;

        const int r1 = wn + brl, r2 = wn + 16 + brl;
        const uint32_t b1B = bB + r1 * 256, b2B = bB + r2 * 256;
        const int r1q = r1 & 7, r2q = r2 & 7;

        #pragma unroll
        for (int k = 0; k < 8; k++) {                // 8 k-steps of K=32
            uint32_t a0,a1,a2,a3, p0,p1,p2,p3, q0,q1,q2,q3;
            LDSM4(a0,a1,a2,a3, aBase + ((((2*k) + ac1) ^ arq) << 4));
            LDSM4(p0,p1,p2,p3, b1B + ((((2*k) + bc1) ^ r1q) << 4));
            LDSM4(q0,q1,q2,q3, b2B + ((((2*k) + bc1) ^ r2q) << 4));
            MMAI(acc[0], a0,a1,a2,a3, p0,p1);
            MMAI(acc[1], a0,a1,a2,a3, p2,p3);
            MMAI(acc[2], a0,a1,a2,a3, q0,q1);
            MMAI(acc[3], a0,a1,a2,a3, q2,q3);
        }

        // epilogue: dist = fl(zn + dot*SCALE_NEG); capture within margin of run-min
        const int colb = ch * 64 + wn + 2 * (lane & 3);
        const int row_lo = rowbase + wm + (lane >> 2);
        #pragma unroll
        for (int j = 0; j < 4; j++) {
            #pragma unroll
            for (int p = 0; p < 4; p++) {
                const int hi = p >> 1;
                float d = __fmaf_rn((float)acc[j][p], SCALE_NEG, hi ? zn_hi : zn_lo);
                float rm = hi ? rm_hi : rm_lo;
                if (d < rm + MARGIN) {
                    int row = row_lo + (hi ? 8 : 0);
                    int pos = atomicAdd(&g_cnt[row], 1);
                    if (pos < CAP) {
                        g_cand [(size_t)row*CAP + pos] = colb + 8*j + (p & 1);
                        g_candd[(size_t)row*CAP + pos] = d;
                    }
                    if (hi) { if (d < rm_hi) rm_hi = d; }
                    else    { if (d < rm_lo) rm_lo = d; }
                }
            }
        }
        rm_lo = fminf(rm_lo, __shfl_xor_sync(0xffffffffu, rm_lo, 1));
        rm_lo = fminf(rm_lo, __shfl_xor_sync(0xffffffffu, rm_lo, 2));
        rm_hi = fminf(rm_hi, __shfl_xor_sync(0xffffffffu, rm_hi, 1));
        rm_hi = fminf(rm_hi, __shfl_xor_sync(0xffffffffu, rm_hi, 2));
    }
}

// ---- Phase 2: exact fp32 rescore (validated) ----
__global__ void phase2_kernel(const float* __restrict__ z, const float* __restrict__ W) {
    const int wid = threadIdx.x >> 5, lane = threadIdx.x & 31;
    const int row = blockIdx.x * 8 + wid;
    const int cnt = g_cnt[row];
    const float zn = g_znorm[row];
    const float* zr = z + (size_t)row * DIM;
    unsigned long long best = 0xFFFFFFFFFFFFFFFFull;

    if (cnt <= CAP) {
        float rmin = 3.4e38f;
        for (int i = lane; i < cnt; i += 32)
            rmin = fminf(rmin, g_candd[(size_t)row*CAP + i]);
        #pragma unroll
        for (int o = 16; o > 0; o >>= 1)
            rmin = fminf(rmin, __shfl_xor_sync(0xffffffffu, rmin, o));
        for (int i = lane; i < cnt; i += 32) {
            float d = g_candd[(size_t)row*CAP + i];
            if (d <= rmin + MARGIN) {
                int idx = g_cand[(size_t)row*CAP + i];
                const float* wr = W + (size_t)idx * DIM;
                float acc = 0.0f;
                #pragma unroll 8
                for (int k = 0; k < DIM; k++) acc = __fmaf_rn(zr[k], wr[k], acc);
                float dist = __fadd_rn(zn, __fmul_rn(-2.0f, acc));
                unsigned long long key =
                    ((unsigned long long)__float_as_uint(dist) << 32) | (unsigned)idx;
                if (key < best) best = key;
            }
        }
    } else {
        for (int c = lane; c < KC; c += 32) {
            const float* wr = W + (size_t)c * DIM;
            float acc = 0.0f;
            #pragma unroll 8
            for (int k = 0; k < DIM; k++) acc = __fmaf_rn(zr[k], wr[k], acc);
            float dist = __fadd_rn(zn, __fmul_rn(-2.0f, acc));
            unsigned long long key =
                ((unsigned long long)__float_as_uint(dist) << 32) | (unsigned)c;
            if (key < best) best = key;
        }
    }
    #pragma unroll
    for (int o = 16; o > 0; o >>= 1) {
        unsigned long long ot = __shfl_xor_sync(0xffffffffu, best, o);
        if (ot < best) best = ot;
    }
    if (lane == 0) g_idx[row] = (int)(best & 0xffffffffu);
}

// ---- output + loss (validated) ----
__global__ void output_kernel(const float* __restrict__ z, const float* __restrict__ W,
                              float* __restrict__ out, int out_size) {
    int row = blockIdx.x, d = threadIdx.x;
    int idx = g_idx[row];
    float zv = z[(size_t)row * DIM + d];
    float wv = W[(size_t)idx * DIM + d];
    float dq  = __fadd_rn(wv, -zv);
    float qst = __fadd_rn(zv, dq);
    if (out_size >= ND) out[(size_t)row * DIM + d] = qst;
    float sq = __fmul_rn(dq, dq);
    __shared__ double sd[DIM];
    sd[d] = (double)sq;
    __syncthreads();
    #pragma unroll
    for (int off = DIM / 2; off > 0; off >>= 1) {
        if (d < off) sd[d] += sd[d + off];
        __syncthreads();
    }
    if (d == 0) {
        g_part[row] = sd[0];
        if (out_size >= ND + 1 + NR) out[ND + 1 + row] = (float)idx;
    }
}
__global__ void finalize1_kernel() {
    __shared__ double sd[256];
    int t = threadIdx.x, b = blockIdx.x;
    sd[t] = g_part[b*512 + t] + g_part[b*512 + 256 + t];
    __syncthreads();
    #pragma unroll
    for (int off = 128; off > 0; off >>= 1) {
        if (t < off) sd[t] += sd[t + off];
        __syncthreads();
    }
    if (t == 0) g_part2[b] = sd[0];
}
__global__ void finalize2_kernel(float* __restrict__ out, int out_size) {
    __shared__ double sd[128];
    int t = threadIdx.x;
    sd[t] = g_part2[t];
    __syncthreads();
    #pragma unroll
    for (int off = 64; off > 0; off >>= 1) {
        if (t < off) sd[t] += sd[t + off];
        __syncthreads();
    }
    if (t == 0 && out_size >= ND + 1) {
        float m = (float)(sd[0] / (double)ND);
        out[ND] = __fadd_rn(m, __fmul_rn(0.25f, m));
    }
}

extern "C" void kernel_launch(void* const* d_in, const int* in_sizes, int n_in,
                              void* d_out, int out_size) {
    const float *z, *W;
    if (in_sizes[0] == NR * DIM) { z = (const float*)d_in[0]; W = (const float*)d_in[1]; }
    else                         { z = (const float*)d_in[1]; W = (const float*)d_in[0]; }
    float* out = (float*)d_out;

    znorm_kernel<<<NR / 8, 256>>>(z);
    wconv_kernel<<<KC * DIM / 256, 256>>>(W);
    dummy_kernel<<<1, 32>>>();                        // phase1 -> 4th launch

    static int done = 0;
    if (!done) {
        cudaFuncSetAttribute(phase1_kernel, cudaFuncAttributeMaxDynamicSharedMemorySize, 49152);
        done = 1;
    }
    phase1_kernel<<<NR / 64, 256, 49152>>>();
    phase2_kernel<<<NR / 8, 256>>>(z, W);

    output_kernel<<<NR, DIM>>>(z, W, out, out_size);
    finalize1_kernel<<<128, 256>>>();
    finalize2_kernel<<<1, 128>>>(out, out_size);
}

// round 13
// speedup vs baseline: 2.6534x; 2.6534x over previous
#include <cuda_runtime.h>
#include <cuda_fp16.h>
#include <stdint.h>

#define NR  65536
#define KC  8192
#define DIM 256
#define ND  (NR*DIM)
#define CAP 64
#define MARGIN 6e-5f
#define NCH 256                 // chunks of 32 codes

__device__ float  g_znorm[NR];
__device__ int    g_idx[NR];
__device__ double g_part[NR];
__device__ double g_part2[128];
__device__ int    g_cnt[NR];
__device__ int    g_cand[(size_t)NR*CAP];
__device__ float  g_candd[(size_t)NR*CAP];
__device__ __align__(128) __half g_zh[ND];
__device__ __align__(128) __half g_wh[KC*DIM];

__device__ __forceinline__ uint32_t smem_u32(const void* p) {
    uint32_t a;
    asm("{ .reg .u64 t; cvta.to.shared.u64 t, %1; cvt.u32.u64 %0, t; }" : "=r"(a) : "l"(p));
    return a;
}
__device__ __forceinline__ void cp16(uint32_t dst, const void* src) {
    asm volatile("cp.async.cg.shared.global [%0], [%1], 16;" :: "r"(dst), "l"(src) : "memory");
}
#define CPC() asm volatile("cp.async.commit_group;" ::: "memory")
#define CPW() asm volatile("cp.async.wait_group 0;" ::: "memory")
#define LDSM4(r0,r1,r2,r3,a) \
    asm volatile("ldmatrix.sync.aligned.m8n8.x4.shared.b16 {%0,%1,%2,%3}, [%4];" \
        : "=r"(r0),"=r"(r1),"=r"(r2),"=r"(r3) : "r"(a))
#define MMA(d,a0,a1,a2,a3,b0,b1) \
    asm volatile("mma.sync.aligned.m16n8k16.row.col.f32.f16.f16.f32 " \
        "{%0,%1,%2,%3}, {%4,%5,%6,%7}, {%8,%9}, {%0,%1,%2,%3};" \
        : "+f"(d[0]),"+f"(d[1]),"+f"(d[2]),"+f"(d[3]) \
        : "r"(a0),"r"(a1),"r"(a2),"r"(a3),"r"(b0),"r"(b1))

// ---- per-row ||z||^2 (validated order) + z->fp16 + zero capture counters ----
__global__ void znorm_kernel(const float* __restrict__ z) {
    int warp = threadIdx.x >> 5, lane = threadIdx.x & 31;
    int row  = blockIdx.x * 8 + warp;
    const float* zr = z + (size_t)row * DIM;
    float s = 0.0f;
    #pragma unroll
    for (int t = 0; t < 8; t++) {
        float v = zr[t * 32 + lane];
        g_zh[(size_t)row * DIM + t * 32 + lane] = __float2half(v);
        s = __fadd_rn(s, __fmul_rn(v, v));
    }
    #pragma unroll
    for (int off = 16; off > 0; off >>= 1)
        s = __fadd_rn(s, __shfl_xor_sync(0xffffffffu, s, off));
    if (lane == 0) { g_znorm[row] = s; g_cnt[row] = 0; }
}
// ---- W -> fp16 scaled by 2^13 (exact) ----
__global__ void wconv_kernel(const float* __restrict__ W) {
    int i = blockIdx.x * 256 + threadIdx.x;
    g_wh[i] = __float2half(W[i] * 8192.0f);
}
// ---- dummy: keeps phase1 in ncu's capture slot ----
__global__ void dummy_kernel() { if (threadIdx.x > 9999) g_part2[0] = 0.0; }

// ---- Phase 1: HMMA f32-acc + capture; 32-code chunks -> 64KB smem, 3 CTA/SM ----
// CTA = 64 rows x all codes. 8 warps: 4(m) x 2(n of 16 cols).
// smem: A 32KB @0, B 2x16KB @32768. Same numerics/margins/capture stats as
// the validated round-3 kernel (each n-group scans its 4096 cols ascending).
// Swizzle (validated): off(r,c16) = r*512 + ((c16 ^ (r&7)) << 4)
__global__ __launch_bounds__(256) void phase1_kernel() {
    extern __shared__ __align__(128) char sm[];
    const int tid = threadIdx.x, lane = tid & 31, wid = tid >> 5;
    const int wm = (wid & 3) * 16, wn = (wid >> 2) * 16;
    const int rowbase = blockIdx.x * 64;
    const uint32_t sb = smem_u32(sm);

    for (int i = tid; i < 2048; i += 256) {          // stage A (z rows, 32KB)
        int r = i >> 5, c = i & 31;
        cp16(sb + r*512 + ((c ^ (r&7)) << 4), g_zh + (size_t)(rowbase+r)*DIM + c*8);
    }
    for (int i = tid; i < 1024; i += 256) {          // stage B chunk 0 (16KB)
        int r = i >> 5, c = i & 31;
        cp16(sb + 32768 + r*512 + ((c ^ (r&7)) << 4), g_wh + (size_t)r*DIM + c*8);
    }
    CPC();

    const float zn_lo = g_znorm[rowbase + wm + (lane >> 2)];
    const float zn_hi = g_znorm[rowbase + wm + 8 + (lane >> 2)];
    float rm_lo = 3.4e38f, rm_hi = 3.4e38f;

    const int ar  = wm + (lane & 15);
    const int ac1 = lane >> 4;
    const uint32_t aBase = sb + ar * 512;
    const int arq = ar & 7;
    const int brl = (lane & 7) + ((lane & 16) >> 1);
    const int bc1 = (lane >> 3) & 1;

    for (int ch = 0; ch < NCH; ch++) {
        const uint32_t bB = sb + 32768 + (ch & 1) * 16384;
        CPW(); __syncthreads();
        if (ch + 1 < NCH) {
            const uint32_t nb = sb + 32768 + ((ch & 1) ^ 1) * 16384;
            const __half* src = g_wh + (size_t)(ch + 1) * 32 * DIM;
            for (int i = tid; i < 1024; i += 256) {
                int r = i >> 5, c = i & 31;
                cp16(nb + r*512 + ((c ^ (r&7)) << 4), src + r*DIM + c*8);
            }
            CPC();
        }
        float acc[2][4];
        #pragma unroll
        for (int j = 0; j < 2; j++)
            #pragma unroll
            for (int p = 0; p < 4; p++) acc[j][p] = 0.0f;

        const int r1 = wn + brl;                     // this warp's 16 B rows
        const uint32_t b1B = bB + r1 * 512;
        const int r1q = r1 & 7;

        #pragma unroll
        for (int k = 0; k < 16; k++) {
            uint32_t a0,a1,a2,a3, p0,p1,p2,p3;
            LDSM4(a0,a1,a2,a3, aBase + ((((2*k) + ac1) ^ arq) << 4));
            LDSM4(p0,p1,p2,p3, b1B + ((((2*k) + bc1) ^ r1q) << 4));
            MMA(acc[0], a0,a1,a2,a3, p0,p1);
            MMA(acc[1], a0,a1,a2,a3, p2,p3);
        }

        // epilogue: dist = fl(zn - acc*2^-12); capture within margin of run-min
        const int colb = ch * 32 + wn + 2 * (lane & 3);
        const int row_lo = rowbase + wm + (lane >> 2);
        #pragma unroll
        for (int j = 0; j < 2; j++) {
            #pragma unroll
            for (int p = 0; p < 4; p++) {
                const int hi = p >> 1;
                float d = __fmaf_rn(acc[j][p], -2.44140625e-4f, hi ? zn_hi : zn_lo);
                float rm = hi ? rm_hi : rm_lo;
                if (d < rm + MARGIN) {
                    int row = row_lo + (hi ? 8 : 0);
                    int pos = atomicAdd(&g_cnt[row], 1);
                    if (pos < CAP) {
                        g_cand [(size_t)row*CAP + pos] = colb + 8*j + (p & 1);
                        g_candd[(size_t)row*CAP + pos] = d;
                    }
                    if (hi) { if (d < rm_hi) rm_hi = d; }
                    else    { if (d < rm_lo) rm_lo = d; }
                }
            }
        }
        rm_lo = fminf(rm_lo, __shfl_xor_sync(0xffffffffu, rm_lo, 1));
        rm_lo = fminf(rm_lo, __shfl_xor_sync(0xffffffffu, rm_lo, 2));
        rm_hi = fminf(rm_hi, __shfl_xor_sync(0xffffffffu, rm_hi, 1));
        rm_hi = fminf(rm_hi, __shfl_xor_sync(0xffffffffu, rm_hi, 2));
    }
}

// ---- Phase 2: exact fp32 rescore (validated) ----
__global__ void phase2_kernel(const float* __restrict__ z, const float* __restrict__ W) {
    const int wid = threadIdx.x >> 5, lane = threadIdx.x & 31;
    const int row = blockIdx.x * 8 + wid;
    const int cnt = g_cnt[row];
    const float zn = g_znorm[row];
    const float* zr = z + (size_t)row * DIM;
    unsigned long long best = 0xFFFFFFFFFFFFFFFFull;

    if (cnt <= CAP) {
        float rmin = 3.4e38f;
        for (int i = lane; i < cnt; i += 32)
            rmin = fminf(rmin, g_candd[(size_t)row*CAP + i]);
        #pragma unroll
        for (int o = 16; o > 0; o >>= 1)
            rmin = fminf(rmin, __shfl_xor_sync(0xffffffffu, rmin, o));
        for (int i = lane; i < cnt; i += 32) {
            float d = g_candd[(size_t)row*CAP + i];
            if (d <= rmin + MARGIN) {
                int idx = g_cand[(size_t)row*CAP + i];
                const float* wr = W + (size_t)idx * DIM;
                float acc = 0.0f;
                #pragma unroll 8
                for (int k = 0; k < DIM; k++) acc = __fmaf_rn(zr[k], wr[k], acc);
                float dist = __fadd_rn(zn, __fmul_rn(-2.0f, acc));
                unsigned long long key =
                    ((unsigned long long)__float_as_uint(dist) << 32) | (unsigned)idx;
                if (key < best) best = key;
            }
        }
    } else {
        for (int c = lane; c < KC; c += 32) {
            const float* wr = W + (size_t)c * DIM;
            float acc = 0.0f;
            #pragma unroll 8
            for (int k = 0; k < DIM; k++) acc = __fmaf_rn(zr[k], wr[k], acc);
            float dist = __fadd_rn(zn, __fmul_rn(-2.0f, acc));
            unsigned long long key =
                ((unsigned long long)__float_as_uint(dist) << 32) | (unsigned)c;
            if (key < best) best = key;
        }
    }
    #pragma unroll
    for (int o = 16; o > 0; o >>= 1) {
        unsigned long long ot = __shfl_xor_sync(0xffffffffu, best, o);
        if (ot < best) best = ot;
    }
    if (lane == 0) g_idx[row] = (int)(best & 0xffffffffu);
}

// ---- output + loss (validated) ----
__global__ void output_kernel(const float* __restrict__ z, const float* __restrict__ W,
                              float* __restrict__ out, int out_size) {
    int row = blockIdx.x, d = threadIdx.x;
    int idx = g_idx[row];
    float zv = z[(size_t)row * DIM + d];
    float wv = W[(size_t)idx * DIM + d];
    float dq  = __fadd_rn(wv, -zv);
    float qst = __fadd_rn(zv, dq);
    if (out_size >= ND) out[(size_t)row * DIM + d] = qst;
    float sq = __fmul_rn(dq, dq);
    __shared__ double sd[DIM];
    sd[d] = (double)sq;
    __syncthreads();
    #pragma unroll
    for (int off = DIM / 2; off > 0; off >>= 1) {
        if (d < off) sd[d] += sd[d + off];
        __syncthreads();
    }
    if (d == 0) {
        g_part[row] = sd[0];
        if (out_size >= ND + 1 + NR) out[ND + 1 + row] = (float)idx;
    }
}
__global__ void finalize1_kernel() {
    __shared__ double sd[256];
    int t = threadIdx.x, b = blockIdx.x;
    sd[t] = g_part[b*512 + t] + g_part[b*512 + 256 + t];
    __syncthreads();
    #pragma unroll
    for (int off = 128; off > 0; off >>= 1) {
        if (t < off) sd[t] += sd[t + off];
        __syncthreads();
    }
    if (t == 0) g_part2[b] = sd[0];
}
__global__ void finalize2_kernel(float* __restrict__ out, int out_size) {
    __shared__ double sd[128];
    int t = threadIdx.x;
    sd[t] = g_part2[t];
    __syncthreads();
    #pragma unroll
    for (int off = 64; off > 0; off >>= 1) {
        if (t < off) sd[t] += sd[t + off];
        __syncthreads();
    }
    if (t == 0 && out_size >= ND + 1) {
        float m = (float)(sd[0] / (double)ND);
        out[ND] = __fadd_rn(m, __fmul_rn(0.25f, m));
    }
}

extern "C" void kernel_launch(void* const* d_in, const int* in_sizes, int n_in,
                              void* d_out, int out_size) {
    const float *z, *W;
    if (in_sizes[0] == NR * DIM) { z = (const float*)d_in[0]; W = (const float*)d_in[1]; }
    else                         { z = (const float*)d_in[1]; W = (const float*)d_in[0]; }
    float* out = (float*)d_out;

    znorm_kernel<<<NR / 8, 256>>>(z);
    wconv_kernel<<<KC * DIM / 256, 256>>>(W);
    dummy_kernel<<<1, 32>>>();                        // phase1 -> 4th launch

    static int done = 0;
    if (!done) {
        cudaFuncSetAttribute(phase1_kernel, cudaFuncAttributeMaxDynamicSharedMemorySize, 65536);
        done = 1;
    }
    phase1_kernel<<<NR / 64, 256, 65536>>>();
    phase2_kernel<<<NR / 8, 256>>>(z, W);

    output_kernel<<<NR, DIM>>>(z, W, out, out_size);
    finalize1_kernel<<<128, 256>>>();
    finalize2_kernel<<<1, 128>>>(out, out_size);
}

// round 15
// speedup vs baseline: 2.9512x; 1.1122x over previous
#include <cuda_runtime.h>
#include <cuda_fp16.h>
#include <stdint.h>

#define NR  65536
#define KC  8192
#define DIM 256
#define ND  (NR*DIM)
#define CAP 64
#define MARGIN 6e-5f

__device__ float  g_znorm[NR];
__device__ int    g_idx[NR];
__device__ double g_part[NR];
__device__ double g_part2[128];
__device__ int    g_cnt[NR];
__device__ int    g_cand[(size_t)NR*CAP];
__device__ float  g_candd[(size_t)NR*CAP];
__device__ __align__(128) __half g_zh[ND];
__device__ __align__(128) __half g_wh[KC*DIM];

__device__ __forceinline__ uint32_t smem_u32(const void* p) {
    uint32_t a;
    asm("{ .reg .u64 t; cvta.to.shared.u64 t, %1; cvt.u32.u64 %0, t; }" : "=r"(a) : "l"(p));
    return a;
}
__device__ __forceinline__ void cp16(uint32_t dst, const void* src) {
    asm volatile("cp.async.cg.shared.global [%0], [%1], 16;" :: "r"(dst), "l"(src) : "memory");
}
#define CPC() asm volatile("cp.async.commit_group;" ::: "memory")
#define CPW() asm volatile("cp.async.wait_group 0;" ::: "memory")
#define LDSM4(r0,r1,r2,r3,a) \
    asm volatile("ldmatrix.sync.aligned.m8n8.x4.shared.b16 {%0,%1,%2,%3}, [%4];" \
        : "=r"(r0),"=r"(r1),"=r"(r2),"=r"(r3) : "r"(a))
#define MMA(d,a0,a1,a2,a3,b0,b1) \
    asm volatile("mma.sync.aligned.m16n8k16.row.col.f32.f16.f16.f32 " \
        "{%0,%1,%2,%3}, {%4,%5,%6,%7}, {%8,%9}, {%0,%1,%2,%3};" \
        : "+f"(d[0]),"+f"(d[1]),"+f"(d[2]),"+f"(d[3]) \
        : "r"(a0),"r"(a1),"r"(a2),"r"(a3),"r"(b0),"r"(b1))

// exact sequential-order dot via float4 loads (FMA order identical to scalar)
__device__ __forceinline__ float dot256_exact(const float* __restrict__ zr,
                                              const float* __restrict__ wr) {
    float acc = 0.0f;
    const float4* z4 = (const float4*)zr;
    const float4* w4 = (const float4*)wr;
    #pragma unroll 8
    for (int k = 0; k < DIM / 4; k++) {
        float4 a = z4[k], b = w4[k];
        acc = __fmaf_rn(a.x, b.x, acc);
        acc = __fmaf_rn(a.y, b.y, acc);
        acc = __fmaf_rn(a.z, b.z, acc);
        acc = __fmaf_rn(a.w, b.w, acc);
    }
    return acc;
}

// ---- per-row ||z||^2 (validated order) + z->fp16 + zero capture counters ----
__global__ void znorm_kernel(const float* __restrict__ z) {
    int warp = threadIdx.x >> 5, lane = threadIdx.x & 31;
    int row  = blockIdx.x * 8 + warp;
    const float* zr = z + (size_t)row * DIM;
    float s = 0.0f;
    #pragma unroll
    for (int t = 0; t < 8; t++) {
        float v = zr[t * 32 + lane];
        g_zh[(size_t)row * DIM + t * 32 + lane] = __float2half(v);
        s = __fadd_rn(s, __fmul_rn(v, v));
    }
    #pragma unroll
    for (int off = 16; off > 0; off >>= 1)
        s = __fadd_rn(s, __shfl_xor_sync(0xffffffffu, s, off));
    if (lane == 0) { g_znorm[row] = s; g_cnt[row] = 0; }
}
// ---- W -> fp16 scaled by 2^13 (exact) ----
__global__ void wconv_kernel(const float* __restrict__ W) {
    int i = blockIdx.x * 256 + threadIdx.x;
    g_wh[i] = __float2half(W[i] * 8192.0f);
}
// ---- dummy: keeps phase1 in ncu's capture slot ----
__global__ void dummy_kernel() { if (threadIdx.x > 9999) g_part2[0] = 0.0; }

// ---- Phase 1: HMMA f32-acc + candidate capture (round-3 validated, 1766us) ----
// CTA = 64 rows x all codes, chunks of 64. 8 warps: 4(m) x 2(n).
// smem: A 32KB @0, B 2x32KB @32768 (96KB, 2 CTA/SM).
// Swizzle (validated): off(r,c16) = r*512 + ((c16 ^ (r&7)) << 4)
__global__ __launch_bounds__(256) void phase1_kernel() {
    extern __shared__ __align__(128) char sm[];
    const int tid = threadIdx.x, lane = tid & 31, wid = tid >> 5;
    const int wm = (wid & 3) * 16, wn = (wid >> 2) * 32;
    const int rowbase = blockIdx.x * 64;
    const uint32_t sb = smem_u32(sm);

    for (int i = tid; i < 2048; i += 256) {          // stage A (z rows)
        int r = i >> 5, c = i & 31;
        cp16(sb + r*512 + ((c ^ (r&7)) << 4), g_zh + (size_t)(rowbase+r)*DIM + c*8);
    }
    for (int i = tid; i < 2048; i += 256) {          // stage B chunk 0
        int r = i >> 5, c = i & 31;
        cp16(sb + 32768 + r*512 + ((c ^ (r&7)) << 4), g_wh + (size_t)r*DIM + c*8);
    }
    CPC();

    const float zn_lo = g_znorm[rowbase + wm + (lane >> 2)];
    const float zn_hi = g_znorm[rowbase + wm + 8 + (lane >> 2)];
    float rm_lo = 3.4e38f, rm_hi = 3.4e38f;

    const int ar  = wm + (lane & 15);
    const int ac1 = lane >> 4;
    const uint32_t aBase = sb + ar * 512;
    const int arq = ar & 7;
    const int brl = (lane & 7) + ((lane & 16) >> 1);
    const int bc1 = (lane >> 3) & 1;

    for (int ch = 0; ch < 128; ch++) {
        const uint32_t bB = sb + 32768 + (ch & 1) * 32768;
        CPW(); __syncthreads();
        if (ch + 1 < 128) {
            const uint32_t nb = sb + 32768 + ((ch & 1) ^ 1) * 32768;
            const __half* src = g_wh + (size_t)(ch + 1) * 64 * DIM;
            for (int i = tid; i < 2048; i += 256) {
                int r = i >> 5, c = i & 31;
                cp16(nb + r*512 + ((c ^ (r&7)) << 4), src + r*DIM + c*8);
            }
            CPC();
        }
        float acc[4][4];
        #pragma unroll
        for (int j = 0; j < 4; j++)
            #pragma unroll
            for (int p = 0; p < 4; p++) acc[j][p] = 0.0f;

        const int r1 = wn + brl, r2 = wn + 16 + brl;
        const uint32_t b1B = bB + r1 * 512, b2B = bB + r2 * 512;
        const int r1q = r1 & 7, r2q = r2 & 7;

        #pragma unroll
        for (int k = 0; k < 16; k++) {
            uint32_t a0,a1,a2,a3, p0,p1,p2,p3, q0,q1,q2,q3;
            LDSM4(a0,a1,a2,a3, aBase + ((((2*k) + ac1) ^ arq) << 4));
            LDSM4(p0,p1,p2,p3, b1B + ((((2*k) + bc1) ^ r1q) << 4));
            LDSM4(q0,q1,q2,q3, b2B + ((((2*k) + bc1) ^ r2q) << 4));
            MMA(acc[0], a0,a1,a2,a3, p0,p1);
            MMA(acc[1], a0,a1,a2,a3, p2,p3);
            MMA(acc[2], a0,a1,a2,a3, q0,q1);
            MMA(acc[3], a0,a1,a2,a3, q2,q3);
        }

        // epilogue: dist = fl(zn - acc*2^-12); capture within margin of run-min
        const int colb = ch * 64 + wn + 2 * (lane & 3);
        const int row_lo = rowbase + wm + (lane >> 2);
        #pragma unroll
        for (int j = 0; j < 4; j++) {
            #pragma unroll
            for (int p = 0; p < 4; p++) {
                const int hi = p >> 1;
                float d = __fmaf_rn(acc[j][p], -2.44140625e-4f, hi ? zn_hi : zn_lo);
                float rm = hi ? rm_hi : rm_lo;
                if (d < rm + MARGIN) {
                    int row = row_lo + (hi ? 8 : 0);
                    int pos = atomicAdd(&g_cnt[row], 1);
                    if (pos < CAP) {
                        g_cand [(size_t)row*CAP + pos] = colb + 8*j + (p & 1);
                        g_candd[(size_t)row*CAP + pos] = d;
                    }
                    if (hi) { if (d < rm_hi) rm_hi = d; }
                    else    { if (d < rm_lo) rm_lo = d; }
                }
            }
        }
        rm_lo = fminf(rm_lo, __shfl_xor_sync(0xffffffffu, rm_lo, 1));
        rm_lo = fminf(rm_lo, __shfl_xor_sync(0xffffffffu, rm_lo, 2));
        rm_hi = fminf(rm_hi, __shfl_xor_sync(0xffffffffu, rm_hi, 1));
        rm_hi = fminf(rm_hi, __shfl_xor_sync(0xffffffffu, rm_hi, 2));
    }
}

// ---- Phase 2: exact fp32 rescore; float4 loads, identical FMA order ----
__global__ void phase2_kernel(const float* __restrict__ z, const float* __restrict__ W) {
    const int wid = threadIdx.x >> 5, lane = threadIdx.x & 31;
    const int row = blockIdx.x * 8 + wid;
    const int cnt = g_cnt[row];
    const float zn = g_znorm[row];
    const float* zr = z + (size_t)row * DIM;
    unsigned long long best = 0xFFFFFFFFFFFFFFFFull;

    if (cnt <= CAP) {
        float rmin = 3.4e38f;
        for (int i = lane; i < cnt; i += 32)
            rmin = fminf(rmin, g_candd[(size_t)row*CAP + i]);
        #pragma unroll
        for (int o = 16; o > 0; o >>= 1)
            rmin = fminf(rmin, __shfl_xor_sync(0xffffffffu, rmin, o));
        for (int i = lane; i < cnt; i += 32) {
            float d = g_candd[(size_t)row*CAP + i];
            if (d <= rmin + MARGIN) {
                int idx = g_cand[(size_t)row*CAP + i];
                float acc = dot256_exact(zr, W + (size_t)idx * DIM);
                float dist = __fadd_rn(zn, __fmul_rn(-2.0f, acc));
                unsigned long long key =
                    ((unsigned long long)__float_as_uint(dist) << 32) | (unsigned)idx;
                if (key < best) best = key;
            }
        }
    } else {
        for (int c = lane; c < KC; c += 32) {
            float acc = dot256_exact(zr, W + (size_t)c * DIM);
            float dist = __fadd_rn(zn, __fmul_rn(-2.0f, acc));
            unsigned long long key =
                ((unsigned long long)__float_as_uint(dist) << 32) | (unsigned)c;
            if (key < best) best = key;
        }
    }
    #pragma unroll
    for (int o = 16; o > 0; o >>= 1) {
        unsigned long long ot = __shfl_xor_sync(0xffffffffu, best, o);
        if (ot < best) best = ot;
    }
    if (lane == 0) g_idx[row] = (int)(best & 0xffffffffu);
}

// ---- output + loss (validated) ----
__global__ void output_kernel(const float* __restrict__ z, const float* __restrict__ W,
                              float* __restrict__ out, int out_size) {
    int row = blockIdx.x, d = threadIdx.x;
    int idx = g_idx[row];
    float zv = z[(size_t)row * DIM + d];
    float wv = W[(size_t)idx * DIM + d];
    float dq  = __fadd_rn(wv, -zv);
    float qst = __fadd_rn(zv, dq);
    if (out_size >= ND) out[(size_t)row * DIM + d] = qst;
    float sq = __fmul_rn(dq, dq);
    __shared__ double sd[DIM];
    sd[d] = (double)sq;
    __syncthreads();
    #pragma unroll
    for (int off = DIM / 2; off > 0; off >>= 1) {
        if (d < off) sd[d] += sd[d + off];
        __syncthreads();
    }
    if (d == 0) {
        g_part[row] = sd[0];
        if (out_size >= ND + 1 + NR) out[ND + 1 + row] = (float)idx;
    }
}
__global__ void finalize1_kernel() {
    __shared__ double sd[256];
    int t = threadIdx.x, b = blockIdx.x;
    sd[t] = g_part[b*512 + t] + g_part[b*512 + 256 + t];
    __syncthreads();
    #pragma unroll
    for (int off = 128; off > 0; off >>= 1) {
        if (t < off) sd[t] += sd[t + off];
        __syncthreads();
    }
    if (t == 0) g_part2[b] = sd[0];
}
__global__ void finalize2_kernel(float* __restrict__ out, int out_size) {
    __shared__ double sd[128];
    int t = threadIdx.x;
    sd[t] = g_part2[t];
    __syncthreads();
    #pragma unroll
    for (int off = 64; off > 0; off >>= 1) {
        if (t < off) sd[t] += sd[t + off];
        __syncthreads();
    }
    if (t == 0 && out_size >= ND + 1) {
        float m = (float)(sd[0] / (double)ND);
        out[ND] = __fadd_rn(m, __fmul_rn(0.25f, m));
    }
}

extern "C" void kernel_launch(void* const* d_in, const int* in_sizes, int n_in,
                              void* d_out, int out_size) {
    const float *z, *W;
    if (in_sizes[0] == NR * DIM) { z = (const float*)d_in[0]; W = (const float*)d_in[1]; }
    else                         { z = (const float*)d_in[1]; W = (const float*)d_in[0]; }
    float* out = (float*)d_out;

    znorm_kernel<<<NR / 8, 256>>>(z);
    wconv_kernel<<<KC * DIM / 256, 256>>>(W);
    dummy_kernel<<<1, 32>>>();                        // phase1 -> 4th launch

    static int done = 0;
    if (!done) {
        cudaFuncSetAttribute(phase1_kernel, cudaFuncAttributeMaxDynamicSharedMemorySize, 98304);
        done = 1;
    }
    phase1_kernel<<<NR / 64, 256, 98304>>>();
    phase2_kernel<<<NR / 8, 256>>>(z, W);

    output_kernel<<<NR, DIM>>>(z, W, out, out_size);
    finalize1_kernel<<<128, 256>>>();
    finalize2_kernel<<<1, 128>>>(out, out_size);
}

// round 16
// speedup vs baseline: 3.3234x; 1.1261x over previous
#include <cuda_runtime.h>
#include <cuda_fp16.h>
#include <stdint.h>

#define NR  65536
#define KC  8192
#define DIM 256
#define ND  (NR*DIM)
#define CAP 64
#define MARGIN 6e-5f

__device__ float  g_znorm[NR];
__device__ int    g_idx[NR];
__device__ double g_part[NR];
__device__ double g_part2[128];
__device__ int    g_cnt[NR];
__device__ int    g_cand[(size_t)NR*CAP];
__device__ float  g_candd[(size_t)NR*CAP];
__device__ __align__(128) __half g_zh[ND];
__device__ __align__(128) __half g_wh[KC*DIM];

__device__ __forceinline__ uint32_t smem_u32(const void* p) {
    uint32_t a;
    asm("{ .reg .u64 t; cvta.to.shared.u64 t, %1; cvt.u32.u64 %0, t; }" : "=r"(a) : "l"(p));
    return a;
}
__device__ __forceinline__ void cp16(uint32_t dst, const void* src) {
    asm volatile("cp.async.cg.shared.global [%0], [%1], 16;" :: "r"(dst), "l"(src) : "memory");
}
#define CPC() asm volatile("cp.async.commit_group;" ::: "memory")
#define CPW() asm volatile("cp.async.wait_group 0;" ::: "memory")
#define LDSM4(r0,r1,r2,r3,a) \
    asm volatile("ldmatrix.sync.aligned.m8n8.x4.shared.b16 {%0,%1,%2,%3}, [%4];" \
        : "=r"(r0),"=r"(r1),"=r"(r2),"=r"(r3) : "r"(a))
#define MMA(d,a0,a1,a2,a3,b0,b1) \
    asm volatile("mma.sync.aligned.m16n8k16.row.col.f32.f16.f16.f32 " \
        "{%0,%1,%2,%3}, {%4,%5,%6,%7}, {%8,%9}, {%0,%1,%2,%3};" \
        : "+f"(d[0]),"+f"(d[1]),"+f"(d[2]),"+f"(d[3]) \
        : "r"(a0),"r"(a1),"r"(a2),"r"(a3),"r"(b0),"r"(b1))

// exact sequential-order dot via float4 loads (FMA order identical to scalar)
__device__ __forceinline__ float dot256_exact(const float* __restrict__ zr,
                                              const float* __restrict__ wr) {
    float acc = 0.0f;
    const float4* z4 = (const float4*)zr;
    const float4* w4 = (const float4*)wr;
    #pragma unroll 8
    for (int k = 0; k < DIM / 4; k++) {
        float4 a = z4[k], b = w4[k];
        acc = __fmaf_rn(a.x, b.x, acc);
        acc = __fmaf_rn(a.y, b.y, acc);
        acc = __fmaf_rn(a.z, b.z, acc);
        acc = __fmaf_rn(a.w, b.w, acc);
    }
    return acc;
}

// ---- per-row ||z||^2 (validated order) + z->fp16 + zero capture counters ----
__global__ void znorm_kernel(const float* __restrict__ z) {
    int warp = threadIdx.x >> 5, lane = threadIdx.x & 31;
    int row  = blockIdx.x * 8 + warp;
    const float* zr = z + (size_t)row * DIM;
    float s = 0.0f;
    #pragma unroll
    for (int t = 0; t < 8; t++) {
        float v = zr[t * 32 + lane];
        g_zh[(size_t)row * DIM + t * 32 + lane] = __float2half(v);
        s = __fadd_rn(s, __fmul_rn(v, v));
    }
    #pragma unroll
    for (int off = 16; off > 0; off >>= 1)
        s = __fadd_rn(s, __shfl_xor_sync(0xffffffffu, s, off));
    if (lane == 0) { g_znorm[row] = s; g_cnt[row] = 0; }
}
// ---- W -> fp16 scaled by 2^13 (exact) ----
__global__ void wconv_kernel(const float* __restrict__ W) {
    int i = blockIdx.x * 256 + threadIdx.x;
    g_wh[i] = __float2half(W[i] * 8192.0f);
}
// ---- dummy: keeps phase1 in ncu's capture slot ----
__global__ void dummy_kernel() { if (threadIdx.x > 9999) g_part2[0] = 0.0; }

// ---- Phase 1: HMMA f32-acc + candidate capture (validated, best) ----
// CTA = 64 rows x all codes, chunks of 64. 8 warps: 4(m) x 2(n).
// smem: A 32KB @0, B 2x32KB @32768 (96KB, 2 CTA/SM).
// Swizzle (validated): off(r,c16) = r*512 + ((c16 ^ (r&7)) << 4)
__global__ __launch_bounds__(256) void phase1_kernel() {
    extern __shared__ __align__(128) char sm[];
    const int tid = threadIdx.x, lane = tid & 31, wid = tid >> 5;
    const int wm = (wid & 3) * 16, wn = (wid >> 2) * 32;
    const int rowbase = blockIdx.x * 64;
    const uint32_t sb = smem_u32(sm);

    for (int i = tid; i < 2048; i += 256) {          // stage A (z rows)
        int r = i >> 5, c = i & 31;
        cp16(sb + r*512 + ((c ^ (r&7)) << 4), g_zh + (size_t)(rowbase+r)*DIM + c*8);
    }
    for (int i = tid; i < 2048; i += 256) {          // stage B chunk 0
        int r = i >> 5, c = i & 31;
        cp16(sb + 32768 + r*512 + ((c ^ (r&7)) << 4), g_wh + (size_t)r*DIM + c*8);
    }
    CPC();

    const float zn_lo = g_znorm[rowbase + wm + (lane >> 2)];
    const float zn_hi = g_znorm[rowbase + wm + 8 + (lane >> 2)];
    float rm_lo = 3.4e38f, rm_hi = 3.4e38f;

    const int ar  = wm + (lane & 15);
    const int ac1 = lane >> 4;
    const uint32_t aBase = sb + ar * 512;
    const int arq = ar & 7;
    const int brl = (lane & 7) + ((lane & 16) >> 1);
    const int bc1 = (lane >> 3) & 1;

    for (int ch = 0; ch < 128; ch++) {
        const uint32_t bB = sb + 32768 + (ch & 1) * 32768;
        CPW(); __syncthreads();
        if (ch + 1 < 128) {
            const uint32_t nb = sb + 32768 + ((ch & 1) ^ 1) * 32768;
            const __half* src = g_wh + (size_t)(ch + 1) * 64 * DIM;
            for (int i = tid; i < 2048; i += 256) {
                int r = i >> 5, c = i & 31;
                cp16(nb + r*512 + ((c ^ (r&7)) << 4), src + r*DIM + c*8);
            }
            CPC();
        }
        float acc[4][4];
        #pragma unroll
        for (int j = 0; j < 4; j++)
            #pragma unroll
            for (int p = 0; p < 4; p++) acc[j][p] = 0.0f;

        const int r1 = wn + brl, r2 = wn + 16 + brl;
        const uint32_t b1B = bB + r1 * 512, b2B = bB + r2 * 512;
        const int r1q = r1 & 7, r2q = r2 & 7;

        #pragma unroll
        for (int k = 0; k < 16; k++) {
            uint32_t a0,a1,a2,a3, p0,p1,p2,p3, q0,q1,q2,q3;
            LDSM4(a0,a1,a2,a3, aBase + ((((2*k) + ac1) ^ arq) << 4));
            LDSM4(p0,p1,p2,p3, b1B + ((((2*k) + bc1) ^ r1q) << 4));
            LDSM4(q0,q1,q2,q3, b2B + ((((2*k) + bc1) ^ r2q) << 4));
            MMA(acc[0], a0,a1,a2,a3, p0,p1);
            MMA(acc[1], a0,a1,a2,a3, p2,p3);
            MMA(acc[2], a0,a1,a2,a3, q0,q1);
            MMA(acc[3], a0,a1,a2,a3, q2,q3);
        }

        // epilogue: dist = fl(zn - acc*2^-12); capture within margin of run-min
        const int colb = ch * 64 + wn + 2 * (lane & 3);
        const int row_lo = rowbase + wm + (lane >> 2);
        #pragma unroll
        for (int j = 0; j < 4; j++) {
            #pragma unroll
            for (int p = 0; p < 4; p++) {
                const int hi = p >> 1;
                float d = __fmaf_rn(acc[j][p], -2.44140625e-4f, hi ? zn_hi : zn_lo);
                float rm = hi ? rm_hi : rm_lo;
                if (d < rm + MARGIN) {
                    int row = row_lo + (hi ? 8 : 0);
                    int pos = atomicAdd(&g_cnt[row], 1);
                    if (pos < CAP) {
                        g_cand [(size_t)row*CAP + pos] = colb + 8*j + (p & 1);
                        g_candd[(size_t)row*CAP + pos] = d;
                    }
                    if (hi) { if (d < rm_hi) rm_hi = d; }
                    else    { if (d < rm_lo) rm_lo = d; }
                }
            }
        }
        rm_lo = fminf(rm_lo, __shfl_xor_sync(0xffffffffu, rm_lo, 1));
        rm_lo = fminf(rm_lo, __shfl_xor_sync(0xffffffffu, rm_lo, 2));
        rm_hi = fminf(rm_hi, __shfl_xor_sync(0xffffffffu, rm_hi, 1));
        rm_hi = fminf(rm_hi, __shfl_xor_sync(0xffffffffu, rm_hi, 2));
    }
}

// ---- Phase 2: exact fp32 rescore; float4 loads, identical FMA order ----
__global__ void phase2_kernel(const float* __restrict__ z, const float* __restrict__ W) {
    const int wid = threadIdx.x >> 5, lane = threadIdx.x & 31;
    const int row = blockIdx.x * 8 + wid;
    const int cnt = g_cnt[row];
    const float zn = g_znorm[row];
    const float* zr = z + (size_t)row * DIM;
    unsigned long long best = 0xFFFFFFFFFFFFFFFFull;

    if (cnt <= CAP) {
        float rmin = 3.4e38f;
        for (int i = lane; i < cnt; i += 32)
            rmin = fminf(rmin, g_candd[(size_t)row*CAP + i]);
        #pragma unroll
        for (int o = 16; o > 0; o >>= 1)
            rmin = fminf(rmin, __shfl_xor_sync(0xffffffffu, rmin, o));
        for (int i = lane; i < cnt; i += 32) {
            float d = g_candd[(size_t)row*CAP + i];
            if (d <= rmin + MARGIN) {
                int idx = g_cand[(size_t)row*CAP + i];
                float acc = dot256_exact(zr, W + (size_t)idx * DIM);
                float dist = __fadd_rn(zn, __fmul_rn(-2.0f, acc));
                unsigned long long key =
                    ((unsigned long long)__float_as_uint(dist) << 32) | (unsigned)idx;
                if (key < best) best = key;
            }
        }
    } else {
        for (int c = lane; c < KC; c += 32) {
            float acc = dot256_exact(zr, W + (size_t)c * DIM);
            float dist = __fadd_rn(zn, __fmul_rn(-2.0f, acc));
            unsigned long long key =
                ((unsigned long long)__float_as_uint(dist) << 32) | (unsigned)c;
            if (key < best) best = key;
        }
    }
    #pragma unroll
    for (int o = 16; o > 0; o >>= 1) {
        unsigned long long ot = __shfl_xor_sync(0xffffffffu, best, o);
        if (ot < best) best = ot;
    }
    if (lane == 0) g_idx[row] = (int)(best & 0xffffffffu);
}

// ---- output + loss: warp-per-row, float4, double shuffle reduction ----
// qst arithmetic elementwise-identical to the validated scalar version.
// Loss partial accumulated in fp64 (order change irrelevant at f32 rounding).
__global__ void output_kernel(const float* __restrict__ z, const float* __restrict__ W,
                              float* __restrict__ out, int out_size) {
    const int warp = threadIdx.x >> 5, lane = threadIdx.x & 31;
    const int row = blockIdx.x * 8 + warp;
    const int idx = g_idx[row];
    const float4* z4 = (const float4*)(z + (size_t)row * DIM);
    const float4* w4 = (const float4*)(W + (size_t)idx * DIM);
    float4* o4 = (float4*)(out + (size_t)row * DIM);

    double s = 0.0;
    #pragma unroll
    for (int t = 0; t < 2; t++) {
        const int i = lane + t * 32;
        float4 zv = z4[i], wv = w4[i];
        float4 dq, q;
        dq.x = __fadd_rn(wv.x, -zv.x);  q.x = __fadd_rn(zv.x, dq.x);
        dq.y = __fadd_rn(wv.y, -zv.y);  q.y = __fadd_rn(zv.y, dq.y);
        dq.z = __fadd_rn(wv.z, -zv.z);  q.z = __fadd_rn(zv.z, dq.z);
        dq.w = __fadd_rn(wv.w, -zv.w);  q.w = __fadd_rn(zv.w, dq.w);
        if (out_size >= ND) o4[i] = q;
        s += (double)__fmul_rn(dq.x, dq.x);
        s += (double)__fmul_rn(dq.y, dq.y);
        s += (double)__fmul_rn(dq.z, dq.z);
        s += (double)__fmul_rn(dq.w, dq.w);
    }
    #pragma unroll
    for (int off = 16; off > 0; off >>= 1)
        s += __shfl_xor_sync(0xffffffffu, s, off);
    if (lane == 0) {
        g_part[row] = s;
        if (out_size >= ND + 1 + NR) out[ND + 1 + row] = (float)idx;
    }
}
__global__ void finalize1_kernel() {
    __shared__ double sd[256];
    int t = threadIdx.x, b = blockIdx.x;
    sd[t] = g_part[b*512 + t] + g_part[b*512 + 256 + t];
    __syncthreads();
    #pragma unroll
    for (int off = 128; off > 0; off >>= 1) {
        if (t < off) sd[t] += sd[t + off];
        __syncthreads();
    }
    if (t == 0) g_part2[b] = sd[0];
}
__global__ void finalize2_kernel(float* __restrict__ out, int out_size) {
    __shared__ double sd[128];
    int t = threadIdx.x;
    sd[t] = g_part2[t];
    __syncthreads();
    #pragma unroll
    for (int off = 64; off > 0; off >>= 1) {
        if (t < off) sd[t] += sd[t + off];
        __syncthreads();
    }
    if (t == 0 && out_size >= ND + 1) {
        float m = (float)(sd[0] / (double)ND);
        out[ND] = __fadd_rn(m, __fmul_rn(0.25f, m));
    }
}

extern "C" void kernel_launch(void* const* d_in, const int* in_sizes, int n_in,
                              void* d_out, int out_size) {
    const float *z, *W;
    if (in_sizes[0] == NR * DIM) { z = (const float*)d_in[0]; W = (const float*)d_in[1]; }
    else                         { z = (const float*)d_in[1]; W = (const float*)d_in[0]; }
    float* out = (float*)d_out;

    znorm_kernel<<<NR / 8, 256>>>(z);
    wconv_kernel<<<KC * DIM / 256, 256>>>(W);
    dummy_kernel<<<1, 32>>>();                        // phase1 -> 4th launch

    static int done = 0;
    if (!done) {
        cudaFuncSetAttribute(phase1_kernel, cudaFuncAttributeMaxDynamicSharedMemorySize, 98304);
        done = 1;
    }
    phase1_kernel<<<NR / 64, 256, 98304>>>();
    phase2_kernel<<<NR / 8, 256>>>(z, W);

    output_kernel<<<NR / 8, 256>>>(z, W, out, out_size);
    finalize1_kernel<<<128, 256>>>();
    finalize2_kernel<<<1, 128>>>(out, out_size);
}